// round 4
// baseline (speedup 1.0000x reference)
#include <cuda_runtime.h>
#include <cuda_fp16.h>
#include <cstdint>

#define T_TOK   2048
#define HID     2048
#define NEXP    64
#define INTER   512
#define SINTER  1024
#define TOPK    8
#define ROWS_SHARED 4096
#define ROWS_MOE    (T_TOK*TOPK)
#define ROWS_TOTAL  (ROWS_SHARED + ROWS_MOE)

#define SAS 40   // smem row stride in halves (K=32 + pad 8)

// ---------------- device scratch ----------------
__device__ float    g_logits[T_TOK*NEXP];
__device__ int      g_sel  [T_TOK*TOPK];
__device__ float    g_selw [T_TOK*TOPK];
__device__ int      g_cnt  [NEXP];
__device__ int      g_off  [NEXP];
__device__ int      g_cur  [NEXP];
__device__ int      g_tok  [ROWS_MOE];
__device__ float    g_tw   [ROWS_MOE];
__device__ int      g_rowof[T_TOK*TOPK];
__device__ float    g_H[(size_t)ROWS_TOTAL*INTER];
__device__ float    g_Y[(size_t)ROWS_TOTAL*HID];

__device__ __forceinline__ uint32_t packh2(float x, float y) {
    __half2 h = __floats2half2_rn(x, y);
    return *(uint32_t*)&h;
}
__device__ __forceinline__ void mma16(float c[4], const uint32_t a[4],
                                      uint32_t b0, uint32_t b1) {
    asm volatile(
        "mma.sync.aligned.m16n8k16.row.col.f32.f16.f16.f32 "
        "{%0,%1,%2,%3}, {%4,%5,%6,%7}, {%8,%9}, {%0,%1,%2,%3};\n"
        : "+f"(c[0]), "+f"(c[1]), "+f"(c[2]), "+f"(c[3])
        : "r"(a[0]), "r"(a[1]), "r"(a[2]), "r"(a[3]), "r"(b0), "r"(b1));
}

// ---------------- 1) router GEMM ----------------
__global__ void router_gemm(const float* __restrict__ x, const float* __restrict__ rw) {
    __shared__ float As[32][33];
    __shared__ float Bs[32][65];
    const int tid = threadIdx.x;
    const int t0  = blockIdx.x * 32;
    const int m   = tid >> 3, nb = tid & 7;
    float acc[8] = {};
    for (int kt = 0; kt < HID; kt += 32) {
        __syncthreads();
        {   int r = tid >> 3, c = (tid & 7) * 4;
            const float4 v = *(const float4*)(x + (size_t)(t0 + r)*HID + kt + c);
            As[r][c] = v.x; As[r][c+1] = v.y; As[r][c+2] = v.z; As[r][c+3] = v.w; }
        #pragma unroll
        for (int i = 0; i < 8; i++) {
            int idx = tid + i*256; int e = idx >> 5, k = idx & 31;
            Bs[k][e] = rw[(size_t)e*HID + kt + k];
        }
        __syncthreads();
        #pragma unroll
        for (int k = 0; k < 32; k++) {
            float a = As[m][k];
            #pragma unroll
            for (int j = 0; j < 8; j++) acc[j] += a * Bs[k][nb + 8*j];
        }
    }
    #pragma unroll
    for (int j = 0; j < 8; j++) g_logits[(size_t)(t0+m)*NEXP + nb + 8*j] = acc[j];
}

// ---------------- 2) top-k ----------------
__global__ void zero_cnt_kernel() { if (threadIdx.x < NEXP) g_cnt[threadIdx.x] = 0; }

__global__ void topk_kernel() {
    int t = blockIdx.x * blockDim.x + threadIdx.x;
    if (t >= T_TOK) return;
    float l[NEXP];
    #pragma unroll
    for (int e = 0; e < NEXP; e++) l[e] = g_logits[(size_t)t*NEXP + e];
    float bw[TOPK]; int bi[TOPK];
    for (int i = 0; i < TOPK; i++) {
        float mv = -1e30f; int mi = 0;
        for (int e = 0; e < NEXP; e++) if (l[e] > mv) { mv = l[e]; mi = e; }
        bw[i] = mv; bi[i] = mi; l[mi] = -1e30f;
    }
    float s = 0.f, mx = bw[0], w[TOPK];
    #pragma unroll
    for (int i = 0; i < TOPK; i++) { w[i] = expf(bw[i] - mx); s += w[i]; }
    float inv = 1.f / s;
    #pragma unroll
    for (int i = 0; i < TOPK; i++) {
        g_sel [t*TOPK+i] = bi[i];
        g_selw[t*TOPK+i] = w[i]*inv;
        atomicAdd(&g_cnt[bi[i]], 1);
    }
}

// ---------------- 3) prefix scan + scatter ----------------
__global__ void scan_kernel() {
    const int i = threadIdx.x;
    __shared__ int tmp[NEXP];
    int v = g_cnt[i];
    tmp[i] = v;
    __syncthreads();
    #pragma unroll
    for (int d = 1; d < NEXP; d <<= 1) {
        int o = (i >= d) ? tmp[i-d] : 0;
        __syncthreads();
        tmp[i] += o;
        __syncthreads();
    }
    int excl = tmp[i] - v;
    g_off[i] = excl; g_cur[i] = excl;
}
__global__ void scatter_kernel() {
    int idx = blockIdx.x*blockDim.x + threadIdx.x;
    if (idx >= T_TOK*TOPK) return;
    int t = idx >> 3;
    int e = g_sel[idx];
    int pos = atomicAdd(&g_cur[e], 1);
    g_tok[pos] = t; g_tw[pos] = g_selw[idx]; g_rowof[idx] = pos;
}

// ---------------- 4) stage 1 (fp16 mma, double-buffered, 512 thr) ----------
// grid (16, 66, 8); M=128, N=64 gate + 64 up, K-tile=32
// smem: s_tok/s_w 1024 | A 2x128x40h | Bg 2x64x40h | Bu 2x64x40h
#define S1_A   1024
#define S1_BG  (S1_A  + 2*128*SAS*2)
#define S1_BU  (S1_BG + 2*64*SAS*2)
#define S1_SMEM (S1_BU + 2*64*SAS*2)
__global__ void __launch_bounds__(512, 1)
stage1_kernel(const float* __restrict__ x,
              const float* __restrict__ wg_,
              const float* __restrict__ wu_,
              const float* __restrict__ sg_,
              const float* __restrict__ su_) {
    const int s = blockIdx.y;
    int nrows, hbase, ldb, offmoe = 0;
    const float *Bg, *Bu;
    if (s < 2) {
        nrows = T_TOK; hbase = s*T_TOK; ldb = SINTER;
        Bg = sg_ + s*INTER; Bu = su_ + s*INTER;
    } else {
        int e = s - 2;
        nrows = g_cnt[e]; offmoe = g_off[e]; hbase = ROWS_SHARED + offmoe; ldb = INTER;
        Bg = wg_ + (size_t)e*HID*INTER; Bu = wu_ + (size_t)e*HID*INTER;
    }
    const int m0 = blockIdx.x * 128;
    if (m0 >= nrows) return;
    const int n0   = blockIdx.z * 64;
    const int nloc = nrows - m0;

    extern __shared__ char smraw[];
    int*    s_tok = (int*)smraw;
    float*  s_w   = (float*)(smraw + 512);
    __half* Ash   = (__half*)(smraw + S1_A);
    __half* Bgs   = (__half*)(smraw + S1_BG);
    __half* Bus   = (__half*)(smraw + S1_BU);

    const int tid = threadIdx.x;
    if (tid < 128) {
        int r = m0 + tid;
        if (r < nrows) {
            if (s < 2) { s_tok[tid] = r; s_w[tid] = 1.f; }
            else       { s_tok[tid] = g_tok[offmoe + r]; s_w[tid] = g_tw[offmoe + r]; }
        } else { s_tok[tid] = -1; s_w[tid] = 0.f; }
    }
    __syncthreads();

    const int lane = tid & 31, warp = tid >> 5;
    const int wm = warp >> 2, wn = warp & 3;      // 4x4 warps; 32 rows x 16 cols each
    const int l4 = lane >> 2, lq = lane & 3;
    float cg[2][2][4] = {}, cu[2][2][4] = {};

    float4 ra[2], rbg, rbu;
    const int ar0 = tid >> 3,         ac0 = (tid & 7) << 2;
    const int ar1 = (tid + 512) >> 3;
    const int bk  = tid >> 4,         bc  = (tid & 15) << 2;

    auto loadT = [&](int kt) {
        int tk0 = s_tok[ar0];
        ra[0] = (tk0 >= 0) ? *(const float4*)(x + (size_t)tk0*HID + kt + ac0)
                           : make_float4(0.f,0.f,0.f,0.f);
        int tk1 = s_tok[ar1];
        ra[1] = (tk1 >= 0) ? *(const float4*)(x + (size_t)tk1*HID + kt + ac0)
                           : make_float4(0.f,0.f,0.f,0.f);
        rbg = *(const float4*)(Bg + (size_t)(kt + bk)*ldb + n0 + bc);
        rbu = *(const float4*)(Bu + (size_t)(kt + bk)*ldb + n0 + bc);
    };
    auto storeT = [&](int buf) {
        {   uint32_t p0 = packh2(ra[0].x, ra[0].y), p1 = packh2(ra[0].z, ra[0].w);
            *(uint2*)(Ash + (buf*128 + ar0)*SAS + ac0) = make_uint2(p0, p1);
            uint32_t q0 = packh2(ra[1].x, ra[1].y), q1 = packh2(ra[1].z, ra[1].w);
            *(uint2*)(Ash + (buf*128 + ar1)*SAS + ac0) = make_uint2(q0, q1); }
        // transposed B: [n][k]
        __half* bg = Bgs + buf*64*SAS;
        __half* bu = Bus + buf*64*SAS;
        bg[(bc+0)*SAS + bk] = __float2half_rn(rbg.x);
        bg[(bc+1)*SAS + bk] = __float2half_rn(rbg.y);
        bg[(bc+2)*SAS + bk] = __float2half_rn(rbg.z);
        bg[(bc+3)*SAS + bk] = __float2half_rn(rbg.w);
        bu[(bc+0)*SAS + bk] = __float2half_rn(rbu.x);
        bu[(bc+1)*SAS + bk] = __float2half_rn(rbu.y);
        bu[(bc+2)*SAS + bk] = __float2half_rn(rbu.z);
        bu[(bc+3)*SAS + bk] = __float2half_rn(rbu.w);
    };
    auto comp = [&](int buf) {
        const __half* Ab = Ash + buf*128*SAS;
        const __half* bg = Bgs + buf*64*SAS;
        const __half* bu = Bus + buf*64*SAS;
        #pragma unroll
        for (int ks = 0; ks < 2; ks++) {          // two k16 steps cover K=32
            const int k0 = ks*16 + 2*lq;
            uint32_t a[2][4];
            #pragma unroll
            for (int mi = 0; mi < 2; mi++) {
                int r = wm*32 + mi*16 + l4;
                a[mi][0] = *(const uint32_t*)(Ab + r*SAS + k0);
                a[mi][1] = *(const uint32_t*)(Ab + (r+8)*SAS + k0);
                a[mi][2] = *(const uint32_t*)(Ab + r*SAS + k0 + 8);
                a[mi][3] = *(const uint32_t*)(Ab + (r+8)*SAS + k0 + 8);
            }
            #pragma unroll
            for (int ni = 0; ni < 2; ni++) {
                int n = wn*16 + ni*8 + l4;
                uint32_t bg0 = *(const uint32_t*)(bg + n*SAS + k0);
                uint32_t bg1 = *(const uint32_t*)(bg + n*SAS + k0 + 8);
                uint32_t bu0 = *(const uint32_t*)(bu + n*SAS + k0);
                uint32_t bu1 = *(const uint32_t*)(bu + n*SAS + k0 + 8);
                mma16(cg[0][ni], a[0], bg0, bg1);
                mma16(cg[1][ni], a[1], bg0, bg1);
                mma16(cu[0][ni], a[0], bu0, bu1);
                mma16(cu[1][ni], a[1], bu0, bu1);
            }
        }
    };

    loadT(0); storeT(0); __syncthreads();
    #pragma unroll 1
    for (int kt = 0, it = 0; kt < HID; kt += 32, it++) {
        int buf = it & 1;
        if (kt + 32 < HID) loadT(kt + 32);
        comp(buf);
        if (kt + 32 < HID) { storeT(buf ^ 1); __syncthreads(); }
    }

    #pragma unroll
    for (int mi = 0; mi < 2; mi++)
        #pragma unroll
        for (int ni = 0; ni < 2; ni++)
            #pragma unroll
            for (int j = 0; j < 4; j++) {
                int r = wm*32 + mi*16 + l4 + ((j >> 1) << 3);
                int c = wn*16 + ni*8 + 2*lq + (j & 1);
                if (r < nloc) {
                    float g = cg[mi][ni][j], u = cu[mi][ni][j];
                    float h = g / (1.f + __expf(-g)) * u * s_w[r];
                    g_H[(size_t)(hbase + m0 + r)*INTER + n0 + c] = h;
                }
            }
}

// ---------------- 5) stage 2 (fp16 mma, double-buffered, 512 thr) ----------
// grid (16, 66, 16); M=128, N=128, K-tile=32
#define S2_B   (2*128*SAS*2)
#define S2_SMEM (S2_B + 2*128*SAS*2)
__global__ void __launch_bounds__(512, 1)
stage2_kernel(const float* __restrict__ wd_,
              const float* __restrict__ sd_) {
    const int s = blockIdx.y;
    int nrows, hbase; const float* Bd;
    if (s < 2) { nrows = T_TOK; hbase = s*T_TOK; Bd = sd_ + (size_t)s*INTER*HID; }
    else { int e = s-2; nrows = g_cnt[e]; hbase = ROWS_SHARED + g_off[e];
           Bd = wd_ + (size_t)e*INTER*HID; }
    const int m0 = blockIdx.x * 128;
    if (m0 >= nrows) return;
    const int n0   = blockIdx.z * 128;
    const int nloc = nrows - m0;

    extern __shared__ char smraw[];
    __half* Ash = (__half*)smraw;
    __half* Bsh = (__half*)(smraw + S2_B);

    const int tid = threadIdx.x, lane = tid & 31, warp = tid >> 5;
    const int wm = warp >> 2, wn = warp & 3;    // 4x4: 32 rows x 32 cols per warp
    const int l4 = lane >> 2, lq = lane & 3;
    float cc[2][4][4] = {};

    float4 ra[2], rb[2];
    const int ar0 = tid >> 3,         ac0 = (tid & 7) << 2;
    const int ar1 = (tid + 512) >> 3;
    const int bk0 = tid >> 5,         bc0 = (tid & 31) << 2;
    const int bk1 = (tid + 512) >> 5;

    auto loadT = [&](int kt) {
        ra[0] = (ar0 < nloc) ? *(const float4*)(g_H + (size_t)(hbase+m0+ar0)*INTER + kt + ac0)
                             : make_float4(0.f,0.f,0.f,0.f);
        ra[1] = (ar1 < nloc) ? *(const float4*)(g_H + (size_t)(hbase+m0+ar1)*INTER + kt + ac0)
                             : make_float4(0.f,0.f,0.f,0.f);
        rb[0] = *(const float4*)(Bd + (size_t)(kt + bk0)*HID + n0 + bc0);
        rb[1] = *(const float4*)(Bd + (size_t)(kt + bk1)*HID + n0 + bc0);
    };
    auto storeT = [&](int buf) {
        {   uint32_t p0 = packh2(ra[0].x, ra[0].y), p1 = packh2(ra[0].z, ra[0].w);
            *(uint2*)(Ash + (buf*128 + ar0)*SAS + ac0) = make_uint2(p0, p1);
            uint32_t q0 = packh2(ra[1].x, ra[1].y), q1 = packh2(ra[1].z, ra[1].w);
            *(uint2*)(Ash + (buf*128 + ar1)*SAS + ac0) = make_uint2(q0, q1); }
        __half* bs = Bsh + buf*128*SAS;
        bs[(bc0+0)*SAS + bk0] = __float2half_rn(rb[0].x);
        bs[(bc0+1)*SAS + bk0] = __float2half_rn(rb[0].y);
        bs[(bc0+2)*SAS + bk0] = __float2half_rn(rb[0].z);
        bs[(bc0+3)*SAS + bk0] = __float2half_rn(rb[0].w);
        bs[(bc0+0)*SAS + bk1] = __float2half_rn(rb[1].x);
        bs[(bc0+1)*SAS + bk1] = __float2half_rn(rb[1].y);
        bs[(bc0+2)*SAS + bk1] = __float2half_rn(rb[1].z);
        bs[(bc0+3)*SAS + bk1] = __float2half_rn(rb[1].w);
    };
    auto comp = [&](int buf) {
        const __half* Ab = Ash + buf*128*SAS;
        const __half* bs = Bsh + buf*128*SAS;
        #pragma unroll
        for (int ks = 0; ks < 2; ks++) {
            const int k0 = ks*16 + 2*lq;
            uint32_t a[2][4];
            #pragma unroll
            for (int mi = 0; mi < 2; mi++) {
                int r = wm*32 + mi*16 + l4;
                a[mi][0] = *(const uint32_t*)(Ab + r*SAS + k0);
                a[mi][1] = *(const uint32_t*)(Ab + (r+8)*SAS + k0);
                a[mi][2] = *(const uint32_t*)(Ab + r*SAS + k0 + 8);
                a[mi][3] = *(const uint32_t*)(Ab + (r+8)*SAS + k0 + 8);
            }
            #pragma unroll
            for (int ni = 0; ni < 4; ni++) {
                int n = wn*32 + ni*8 + l4;
                uint32_t b0 = *(const uint32_t*)(bs + n*SAS + k0);
                uint32_t b1 = *(const uint32_t*)(bs + n*SAS + k0 + 8);
                mma16(cc[0][ni], a[0], b0, b1);
                mma16(cc[1][ni], a[1], b0, b1);
            }
        }
    };

    loadT(0); storeT(0); __syncthreads();
    #pragma unroll 1
    for (int kt = 0, it = 0; kt < INTER; kt += 32, it++) {
        int buf = it & 1;
        if (kt + 32 < INTER) loadT(kt + 32);
        comp(buf);
        if (kt + 32 < INTER) { storeT(buf ^ 1); __syncthreads(); }
    }

    #pragma unroll
    for (int mi = 0; mi < 2; mi++)
        #pragma unroll
        for (int ni = 0; ni < 4; ni++) {
            int r0 = wm*32 + mi*16 + l4;
            int c0 = wn*32 + ni*8 + 2*lq;
            if (r0 < nloc)
                *(float2*)(g_Y + (size_t)(hbase+m0+r0)*HID + n0 + c0) =
                    make_float2(cc[mi][ni][0], cc[mi][ni][1]);
            int r1 = r0 + 8;
            if (r1 < nloc)
                *(float2*)(g_Y + (size_t)(hbase+m0+r1)*HID + n0 + c0) =
                    make_float2(cc[mi][ni][2], cc[mi][ni][3]);
        }
}

// ---------------- 6) combine ----------------
__global__ void combine_kernel(float* __restrict__ out) {
    const int t = blockIdx.x;
    __shared__ int rows[10];
    const int tid = threadIdx.x;
    if (tid < 8)       rows[tid] = ROWS_SHARED + g_rowof[t*TOPK + tid];
    else if (tid == 8) rows[8] = t;
    else if (tid == 9) rows[9] = T_TOK + t;
    __syncthreads();
    for (int c = tid*4; c < HID; c += 1024) {
        float4 acc = make_float4(0.f,0.f,0.f,0.f);
        #pragma unroll
        for (int j = 0; j < 10; j++) {
            const float4 v = *(const float4*)(g_Y + (size_t)rows[j]*HID + c);
            acc.x += v.x; acc.y += v.y; acc.z += v.z; acc.w += v.w;
        }
        *(float4*)(out + (size_t)t*HID + c) = acc;
    }
}

// ---------------- launch ----------------
extern "C" void kernel_launch(void* const* d_in, const int* in_sizes, int n_in,
                              void* d_out, int out_size) {
    const float* x  = (const float*)d_in[0];
    const float* rw = (const float*)d_in[1];
    const float* wg = (const float*)d_in[2];
    const float* wu = (const float*)d_in[3];
    const float* wd = (const float*)d_in[4];
    const float* sg = (const float*)d_in[5];
    const float* su = (const float*)d_in[6];
    const float* sd = (const float*)d_in[7];
    float* out = (float*)d_out;

    static bool attr_done = false;
    if (!attr_done) {
        cudaFuncSetAttribute(stage1_kernel, cudaFuncAttributeMaxDynamicSharedMemorySize, S1_SMEM);
        cudaFuncSetAttribute(stage2_kernel, cudaFuncAttributeMaxDynamicSharedMemorySize, S2_SMEM);
        attr_done = true;
    }

    router_gemm   <<<64, 256>>>(x, rw);
    zero_cnt_kernel<<<1, 64>>>();
    topk_kernel   <<<8, 256>>>();
    scan_kernel   <<<1, 64>>>();
    scatter_kernel<<<64, 256>>>();
    stage1_kernel <<<dim3(16, 66, 8),  512, S1_SMEM>>>(x, wg, wu, sg, su);
    stage2_kernel <<<dim3(16, 66, 16), 512, S2_SMEM>>>(wd, sd);
    combine_kernel<<<2048, 256>>>(out);
}

// round 5
// speedup vs baseline: 2.3614x; 2.3614x over previous
#include <cuda_runtime.h>
#include <cuda_fp16.h>
#include <cstdint>

#define T_TOK   2048
#define HID     2048
#define NEXP    64
#define INTER   512
#define SINTER  1024
#define TOPK    8
#define ROWS_SHARED 4096
#define ROWS_MOE    (T_TOK*TOPK)
#define ROWS_TOTAL  (ROWS_SHARED + ROWS_MOE)

#define SAS  40   // A smem row stride (halves): K=32 + pad 8
#define SBS1 72   // stage1 B row stride (halves): N=64 + pad 8
#define SBS2 136  // stage2 B row stride (halves): N=128 + pad 8

// ---------------- device scratch ----------------
__device__ float    g_logits[T_TOK*NEXP];
__device__ int      g_sel  [T_TOK*TOPK];
__device__ float    g_selw [T_TOK*TOPK];
__device__ int      g_cnt  [NEXP];
__device__ int      g_off  [NEXP];
__device__ int      g_cur  [NEXP];
__device__ int      g_tok  [ROWS_MOE];
__device__ float    g_tw   [ROWS_MOE];
__device__ int      g_rowof[T_TOK*TOPK];
__device__ float    g_H[(size_t)ROWS_TOTAL*INTER];
__device__ float    g_Y[(size_t)ROWS_TOTAL*HID];

// ---------------- helpers ----------------
__device__ __forceinline__ uint32_t smem_u32(const void* p) {
    uint32_t a;
    asm("{ .reg .u64 t; cvta.to.shared.u64 t, %1; cvt.u32.u64 %0, t; }" : "=r"(a) : "l"(p));
    return a;
}
__device__ __forceinline__ uint32_t packh2(float x, float y) {
    __half2 h = __floats2half2_rn(x, y);
    return *(uint32_t*)&h;
}
__device__ __forceinline__ void mma16(float c[4], const uint32_t a[4],
                                      uint32_t b0, uint32_t b1) {
    asm volatile(
        "mma.sync.aligned.m16n8k16.row.col.f32.f16.f16.f32 "
        "{%0,%1,%2,%3}, {%4,%5,%6,%7}, {%8,%9}, {%0,%1,%2,%3};\n"
        : "+f"(c[0]), "+f"(c[1]), "+f"(c[2]), "+f"(c[3])
        : "r"(a[0]), "r"(a[1]), "r"(a[2]), "r"(a[3]), "r"(b0), "r"(b1));
}
__device__ __forceinline__ void ldsm_x4(uint32_t r[4], uint32_t addr) {
    asm volatile("ldmatrix.sync.aligned.m8n8.x4.shared.b16 {%0,%1,%2,%3}, [%4];"
        : "=r"(r[0]), "=r"(r[1]), "=r"(r[2]), "=r"(r[3]) : "r"(addr));
}
__device__ __forceinline__ void ldsm_x4t(uint32_t r[4], uint32_t addr) {
    asm volatile("ldmatrix.sync.aligned.m8n8.x4.trans.shared.b16 {%0,%1,%2,%3}, [%4];"
        : "=r"(r[0]), "=r"(r[1]), "=r"(r[2]), "=r"(r[3]) : "r"(addr));
}

// ---------------- 1) router GEMM ----------------
__global__ void router_gemm(const float* __restrict__ x, const float* __restrict__ rw) {
    __shared__ float As[32][33];
    __shared__ float Bs[32][65];
    const int tid = threadIdx.x;
    const int t0  = blockIdx.x * 32;
    const int m   = tid >> 3, nb = tid & 7;
    float acc[8] = {};
    for (int kt = 0; kt < HID; kt += 32) {
        __syncthreads();
        {   int r = tid >> 3, c = (tid & 7) * 4;
            const float4 v = *(const float4*)(x + (size_t)(t0 + r)*HID + kt + c);
            As[r][c] = v.x; As[r][c+1] = v.y; As[r][c+2] = v.z; As[r][c+3] = v.w; }
        #pragma unroll
        for (int i = 0; i < 8; i++) {
            int idx = tid + i*256; int e = idx >> 5, k = idx & 31;
            Bs[k][e] = rw[(size_t)e*HID + kt + k];
        }
        __syncthreads();
        #pragma unroll
        for (int k = 0; k < 32; k++) {
            float a = As[m][k];
            #pragma unroll
            for (int j = 0; j < 8; j++) acc[j] += a * Bs[k][nb + 8*j];
        }
    }
    #pragma unroll
    for (int j = 0; j < 8; j++) g_logits[(size_t)(t0+m)*NEXP + nb + 8*j] = acc[j];
}

// ---------------- 2) top-k ----------------
__global__ void zero_cnt_kernel() { if (threadIdx.x < NEXP) g_cnt[threadIdx.x] = 0; }

__global__ void topk_kernel() {
    int t = blockIdx.x * blockDim.x + threadIdx.x;
    if (t >= T_TOK) return;
    float l[NEXP];
    #pragma unroll
    for (int e = 0; e < NEXP; e++) l[e] = g_logits[(size_t)t*NEXP + e];
    float bw[TOPK]; int bi[TOPK];
    for (int i = 0; i < TOPK; i++) {
        float mv = -1e30f; int mi = 0;
        for (int e = 0; e < NEXP; e++) if (l[e] > mv) { mv = l[e]; mi = e; }
        bw[i] = mv; bi[i] = mi; l[mi] = -1e30f;
    }
    float s = 0.f, mx = bw[0], w[TOPK];
    #pragma unroll
    for (int i = 0; i < TOPK; i++) { w[i] = expf(bw[i] - mx); s += w[i]; }
    float inv = 1.f / s;
    #pragma unroll
    for (int i = 0; i < TOPK; i++) {
        g_sel [t*TOPK+i] = bi[i];
        g_selw[t*TOPK+i] = w[i]*inv;
        atomicAdd(&g_cnt[bi[i]], 1);
    }
}

// ---------------- 3) prefix scan + scatter ----------------
__global__ void scan_kernel() {
    const int i = threadIdx.x;
    __shared__ int tmp[NEXP];
    int v = g_cnt[i];
    tmp[i] = v;
    __syncthreads();
    #pragma unroll
    for (int d = 1; d < NEXP; d <<= 1) {
        int o = (i >= d) ? tmp[i-d] : 0;
        __syncthreads();
        tmp[i] += o;
        __syncthreads();
    }
    int excl = tmp[i] - v;
    g_off[i] = excl; g_cur[i] = excl;
}
__global__ void scatter_kernel() {
    int idx = blockIdx.x*blockDim.x + threadIdx.x;
    if (idx >= T_TOK*TOPK) return;
    int t = idx >> 3;
    int e = g_sel[idx];
    int pos = atomicAdd(&g_cur[e], 1);
    g_tok[pos] = t; g_tw[pos] = g_selw[idx]; g_rowof[idx] = pos;
}

// ---------------- 4) stage 1 (fp16 mma + ldmatrix, double-buffered) --------
// grid (16, 66, 8); M=128, N=64 gate + 64 up, K-tile=32, 512 threads
#define S1_A    1024
#define S1_BG   (S1_A  + 2*128*SAS*2)
#define S1_BU   (S1_BG + 2*32*SBS1*2)
#define S1_SMEM (S1_BU + 2*32*SBS1*2)
__global__ void __launch_bounds__(512, 1)
stage1_kernel(const float* __restrict__ x,
              const float* __restrict__ wg_,
              const float* __restrict__ wu_,
              const float* __restrict__ sg_,
              const float* __restrict__ su_) {
    const int s = blockIdx.y;
    int nrows, hbase, ldb, offmoe = 0;
    const float *Bg, *Bu;
    if (s < 2) {
        nrows = T_TOK; hbase = s*T_TOK; ldb = SINTER;
        Bg = sg_ + s*INTER; Bu = su_ + s*INTER;
    } else {
        int e = s - 2;
        nrows = g_cnt[e]; offmoe = g_off[e]; hbase = ROWS_SHARED + offmoe; ldb = INTER;
        Bg = wg_ + (size_t)e*HID*INTER; Bu = wu_ + (size_t)e*HID*INTER;
    }
    const int m0 = blockIdx.x * 128;
    if (m0 >= nrows) return;
    const int n0   = blockIdx.z * 64;
    const int nloc = nrows - m0;

    extern __shared__ char smraw[];
    int*    s_tok = (int*)smraw;
    float*  s_w   = (float*)(smraw + 512);
    __half* Ash   = (__half*)(smraw + S1_A);
    __half* Bgs   = (__half*)(smraw + S1_BG);
    __half* Bus   = (__half*)(smraw + S1_BU);
    const uint32_t aB  = smem_u32(Ash);
    const uint32_t bgB = smem_u32(Bgs);
    const uint32_t buB = smem_u32(Bus);

    const int tid = threadIdx.x;
    if (tid < 128) {
        int r = m0 + tid;
        if (r < nrows) {
            if (s < 2) { s_tok[tid] = r; s_w[tid] = 1.f; }
            else       { s_tok[tid] = g_tok[offmoe + r]; s_w[tid] = g_tw[offmoe + r]; }
        } else { s_tok[tid] = -1; s_w[tid] = 0.f; }
    }
    __syncthreads();

    const int lane = tid & 31, warp = tid >> 5;
    const int wm = warp >> 2, wn = warp & 3;      // 4x4 warps: 32m x 16n
    const int l4 = lane >> 2, lq = lane & 3;
    const int lr = lane & 15, lc = lane >> 4;
    float cg[2][2][4] = {}, cu[2][2][4] = {};

    // ldmatrix base offsets (bytes)
    const uint32_t aFrag = aB  + (uint32_t)(wm*32 + lr)*(SAS*2)  + lc*16;
    const uint32_t gFrag = bgB + (uint32_t)lr*(SBS1*2) + wn*32 + lc*16;
    const uint32_t uFrag = buB + (uint32_t)lr*(SBS1*2) + wn*32 + lc*16;

    float4 ra[2], rbg, rbu;
    const int ar0 = tid >> 3,         ac0 = (tid & 7) << 2;
    const int ar1 = (tid + 512) >> 3;
    const int bk  = tid >> 4,         bc  = (tid & 15) << 2;

    auto loadT = [&](int kt) {
        int tk0 = s_tok[ar0];
        ra[0] = (tk0 >= 0) ? *(const float4*)(x + (size_t)tk0*HID + kt + ac0)
                           : make_float4(0.f,0.f,0.f,0.f);
        int tk1 = s_tok[ar1];
        ra[1] = (tk1 >= 0) ? *(const float4*)(x + (size_t)tk1*HID + kt + ac0)
                           : make_float4(0.f,0.f,0.f,0.f);
        rbg = *(const float4*)(Bg + (size_t)(kt + bk)*ldb + n0 + bc);
        rbu = *(const float4*)(Bu + (size_t)(kt + bk)*ldb + n0 + bc);
    };
    auto storeT = [&](int buf) {
        *(uint2*)(Ash + (buf*128 + ar0)*SAS + ac0) =
            make_uint2(packh2(ra[0].x, ra[0].y), packh2(ra[0].z, ra[0].w));
        *(uint2*)(Ash + (buf*128 + ar1)*SAS + ac0) =
            make_uint2(packh2(ra[1].x, ra[1].y), packh2(ra[1].z, ra[1].w));
        *(uint2*)(Bgs + (buf*32 + bk)*SBS1 + bc) =
            make_uint2(packh2(rbg.x, rbg.y), packh2(rbg.z, rbg.w));
        *(uint2*)(Bus + (buf*32 + bk)*SBS1 + bc) =
            make_uint2(packh2(rbu.x, rbu.y), packh2(rbu.z, rbu.w));
    };
    auto comp = [&](int buf) {
        const uint32_t aOff = aFrag + (uint32_t)buf*(128*SAS*2);
        const uint32_t gOff = gFrag + (uint32_t)buf*(32*SBS1*2);
        const uint32_t uOff = uFrag + (uint32_t)buf*(32*SBS1*2);
        #pragma unroll
        for (int ks = 0; ks < 2; ks++) {          // two k16 steps cover K=32
            uint32_t a0[4], a1[4], bg[4], bu[4];
            ldsm_x4 (a0, aOff + ks*32);
            ldsm_x4 (a1, aOff + 16*(SAS*2) + ks*32);
            ldsm_x4t(bg, gOff + ks*16*(SBS1*2));
            ldsm_x4t(bu, uOff + ks*16*(SBS1*2));
            #pragma unroll
            for (int ni = 0; ni < 2; ni++) {
                mma16(cg[0][ni], a0, bg[2*ni], bg[2*ni+1]);
                mma16(cg[1][ni], a1, bg[2*ni], bg[2*ni+1]);
                mma16(cu[0][ni], a0, bu[2*ni], bu[2*ni+1]);
                mma16(cu[1][ni], a1, bu[2*ni], bu[2*ni+1]);
            }
        }
    };

    loadT(0); storeT(0); __syncthreads();
    #pragma unroll 1
    for (int kt = 0, it = 0; kt < HID; kt += 32, it++) {
        int buf = it & 1;
        if (kt + 32 < HID) loadT(kt + 32);
        comp(buf);
        if (kt + 32 < HID) { storeT(buf ^ 1); __syncthreads(); }
    }

    #pragma unroll
    for (int mi = 0; mi < 2; mi++)
        #pragma unroll
        for (int ni = 0; ni < 2; ni++)
            #pragma unroll
            for (int j = 0; j < 4; j++) {
                int r = wm*32 + mi*16 + l4 + ((j >> 1) << 3);
                int c = wn*16 + ni*8 + 2*lq + (j & 1);
                if (r < nloc) {
                    float g = cg[mi][ni][j], u = cu[mi][ni][j];
                    float h = g / (1.f + __expf(-g)) * u * s_w[r];
                    g_H[(size_t)(hbase + m0 + r)*INTER + n0 + c] = h;
                }
            }
}

// ---------------- 5) stage 2 (fp16 mma + ldmatrix, double-buffered) --------
// grid (16, 66, 16); M=128, N=128, K-tile=32, 512 threads
#define S2_B    (2*128*SAS*2)
#define S2_SMEM (S2_B + 2*32*SBS2*2)
__global__ void __launch_bounds__(512, 1)
stage2_kernel(const float* __restrict__ wd_,
              const float* __restrict__ sd_) {
    const int s = blockIdx.y;
    int nrows, hbase; const float* Bd;
    if (s < 2) { nrows = T_TOK; hbase = s*T_TOK; Bd = sd_ + (size_t)s*INTER*HID; }
    else { int e = s-2; nrows = g_cnt[e]; hbase = ROWS_SHARED + g_off[e];
           Bd = wd_ + (size_t)e*INTER*HID; }
    const int m0 = blockIdx.x * 128;
    if (m0 >= nrows) return;
    const int n0   = blockIdx.z * 128;
    const int nloc = nrows - m0;

    extern __shared__ char smraw[];
    __half* Ash = (__half*)smraw;
    __half* Bsh = (__half*)(smraw + S2_B);
    const uint32_t aB = smem_u32(Ash);
    const uint32_t bB = smem_u32(Bsh);

    const int tid = threadIdx.x, lane = tid & 31, warp = tid >> 5;
    const int wm = warp >> 2, wn = warp & 3;    // 4x4: 32m x 32n per warp
    const int l4 = lane >> 2, lq = lane & 3;
    const int lr = lane & 15, lc = lane >> 4;
    float cc[2][4][4] = {};

    const uint32_t aFrag = aB + (uint32_t)(wm*32 + lr)*(SAS*2) + lc*16;
    const uint32_t bFrag = bB + (uint32_t)lr*(SBS2*2) + wn*64 + lc*16;

    float4 ra[2], rb[2];
    const int ar0 = tid >> 3,         ac0 = (tid & 7) << 2;
    const int ar1 = (tid + 512) >> 3;
    const int bk0 = tid >> 5,         bc0 = (tid & 31) << 2;
    const int bk1 = bk0 + 16;

    auto loadT = [&](int kt) {
        ra[0] = (ar0 < nloc) ? *(const float4*)(g_H + (size_t)(hbase+m0+ar0)*INTER + kt + ac0)
                             : make_float4(0.f,0.f,0.f,0.f);
        ra[1] = (ar1 < nloc) ? *(const float4*)(g_H + (size_t)(hbase+m0+ar1)*INTER + kt + ac0)
                             : make_float4(0.f,0.f,0.f,0.f);
        rb[0] = *(const float4*)(Bd + (size_t)(kt + bk0)*HID + n0 + bc0);
        rb[1] = *(const float4*)(Bd + (size_t)(kt + bk1)*HID + n0 + bc0);
    };
    auto storeT = [&](int buf) {
        *(uint2*)(Ash + (buf*128 + ar0)*SAS + ac0) =
            make_uint2(packh2(ra[0].x, ra[0].y), packh2(ra[0].z, ra[0].w));
        *(uint2*)(Ash + (buf*128 + ar1)*SAS + ac0) =
            make_uint2(packh2(ra[1].x, ra[1].y), packh2(ra[1].z, ra[1].w));
        *(uint2*)(Bsh + (buf*32 + bk0)*SBS2 + bc0) =
            make_uint2(packh2(rb[0].x, rb[0].y), packh2(rb[0].z, rb[0].w));
        *(uint2*)(Bsh + (buf*32 + bk1)*SBS2 + bc0) =
            make_uint2(packh2(rb[1].x, rb[1].y), packh2(rb[1].z, rb[1].w));
    };
    auto comp = [&](int buf) {
        const uint32_t aOff = aFrag + (uint32_t)buf*(128*SAS*2);
        const uint32_t bOff = bFrag + (uint32_t)buf*(32*SBS2*2);
        #pragma unroll
        for (int ks = 0; ks < 2; ks++) {
            uint32_t a0[4], a1[4], b0[4], b1[4];
            ldsm_x4 (a0, aOff + ks*32);
            ldsm_x4 (a1, aOff + 16*(SAS*2) + ks*32);
            ldsm_x4t(b0, bOff + ks*16*(SBS2*2));
            ldsm_x4t(b1, bOff + ks*16*(SBS2*2) + 32);
            #pragma unroll
            for (int p = 0; p < 2; p++) {
                const uint32_t* bp = p ? b1 : b0;
                #pragma unroll
                for (int q = 0; q < 2; q++) {
                    mma16(cc[0][p*2+q], a0, bp[2*q], bp[2*q+1]);
                    mma16(cc[1][p*2+q], a1, bp[2*q], bp[2*q+1]);
                }
            }
        }
    };

    loadT(0); storeT(0); __syncthreads();
    #pragma unroll 1
    for (int kt = 0, it = 0; kt < INTER; kt += 32, it++) {
        int buf = it & 1;
        if (kt + 32 < INTER) loadT(kt + 32);
        comp(buf);
        if (kt + 32 < INTER) { storeT(buf ^ 1); __syncthreads(); }
    }

    #pragma unroll
    for (int mi = 0; mi < 2; mi++)
        #pragma unroll
        for (int ni = 0; ni < 4; ni++) {
            int r0 = wm*32 + mi*16 + l4;
            int c0 = wn*32 + ni*8 + 2*lq;
            if (r0 < nloc)
                *(float2*)(g_Y + (size_t)(hbase+m0+r0)*HID + n0 + c0) =
                    make_float2(cc[mi][ni][0], cc[mi][ni][1]);
            int r1 = r0 + 8;
            if (r1 < nloc)
                *(float2*)(g_Y + (size_t)(hbase+m0+r1)*HID + n0 + c0) =
                    make_float2(cc[mi][ni][2], cc[mi][ni][3]);
        }
}

// ---------------- 6) combine ----------------
__global__ void combine_kernel(float* __restrict__ out) {
    const int t = blockIdx.x;
    __shared__ int rows[10];
    const int tid = threadIdx.x;
    if (tid < 8)       rows[tid] = ROWS_SHARED + g_rowof[t*TOPK + tid];
    else if (tid == 8) rows[8] = t;
    else if (tid == 9) rows[9] = T_TOK + t;
    __syncthreads();
    for (int c = tid*4; c < HID; c += 1024) {
        float4 acc = make_float4(0.f,0.f,0.f,0.f);
        #pragma unroll
        for (int j = 0; j < 10; j++) {
            const float4 v = *(const float4*)(g_Y + (size_t)rows[j]*HID + c);
            acc.x += v.x; acc.y += v.y; acc.z += v.z; acc.w += v.w;
        }
        *(float4*)(out + (size_t)t*HID + c) = acc;
    }
}

// ---------------- launch ----------------
extern "C" void kernel_launch(void* const* d_in, const int* in_sizes, int n_in,
                              void* d_out, int out_size) {
    const float* x  = (const float*)d_in[0];
    const float* rw = (const float*)d_in[1];
    const float* wg = (const float*)d_in[2];
    const float* wu = (const float*)d_in[3];
    const float* wd = (const float*)d_in[4];
    const float* sg = (const float*)d_in[5];
    const float* su = (const float*)d_in[6];
    const float* sd = (const float*)d_in[7];
    float* out = (float*)d_out;

    static bool attr_done = false;
    if (!attr_done) {
        cudaFuncSetAttribute(stage1_kernel, cudaFuncAttributeMaxDynamicSharedMemorySize, S1_SMEM);
        cudaFuncSetAttribute(stage2_kernel, cudaFuncAttributeMaxDynamicSharedMemorySize, S2_SMEM);
        attr_done = true;
    }

    router_gemm   <<<64, 256>>>(x, rw);
    zero_cnt_kernel<<<1, 64>>>();
    topk_kernel   <<<8, 256>>>();
    scan_kernel   <<<1, 64>>>();
    scatter_kernel<<<64, 256>>>();
    stage1_kernel <<<dim3(16, 66, 8),  512, S1_SMEM>>>(x, wg, wu, sg, su);
    stage2_kernel <<<dim3(16, 66, 16), 512, S2_SMEM>>>(wd, sd);
    combine_kernel<<<2048, 256>>>(out);
}

// round 6
// speedup vs baseline: 2.8997x; 1.2279x over previous
#include <cuda_runtime.h>
#include <cuda_fp16.h>
#include <cstdint>

#define T_TOK   2048
#define HID     2048
#define NEXP    64
#define INTER   512
#define SINTER  1024
#define TOPK    8
#define ROWS_SHARED 4096
#define ROWS_MOE    (T_TOK*TOPK)
#define ROWS_TOTAL  (ROWS_SHARED + ROWS_MOE)

#define SA   72   // A smem row stride (halves): K=64 + pad 8
#define SB1  72   // stage1 B row stride (halves): N=64 + pad 8
#define SB2  136  // stage2 B row stride (halves): N=128 + pad 8

// ---------------- device scratch ----------------
__device__ float    g_logits[T_TOK*NEXP];
__device__ int      g_sel  [T_TOK*TOPK];
__device__ float    g_selw [T_TOK*TOPK];
__device__ int      g_cnt  [NEXP];
__device__ int      g_off  [NEXP];
__device__ int      g_cur  [NEXP];
__device__ int      g_tok  [ROWS_MOE];
__device__ float    g_tw   [ROWS_MOE];
__device__ int      g_rowof[T_TOK*TOPK];
__device__ float    g_H[(size_t)ROWS_TOTAL*INTER];
__device__ float    g_Y[(size_t)ROWS_TOTAL*HID];

// ---------------- helpers ----------------
__device__ __forceinline__ uint32_t smem_u32(const void* p) {
    uint32_t a;
    asm("{ .reg .u64 t; cvta.to.shared.u64 t, %1; cvt.u32.u64 %0, t; }" : "=r"(a) : "l"(p));
    return a;
}
__device__ __forceinline__ uint32_t packh2(float x, float y) {
    __half2 h = __floats2half2_rn(x, y);
    return *(uint32_t*)&h;
}
__device__ __forceinline__ void mma16(float c[4], const uint32_t a[4],
                                      uint32_t b0, uint32_t b1) {
    asm volatile(
        "mma.sync.aligned.m16n8k16.row.col.f32.f16.f16.f32 "
        "{%0,%1,%2,%3}, {%4,%5,%6,%7}, {%8,%9}, {%0,%1,%2,%3};\n"
        : "+f"(c[0]), "+f"(c[1]), "+f"(c[2]), "+f"(c[3])
        : "r"(a[0]), "r"(a[1]), "r"(a[2]), "r"(a[3]), "r"(b0), "r"(b1));
}
__device__ __forceinline__ void ldsm_x4(uint32_t r[4], uint32_t addr) {
    asm volatile("ldmatrix.sync.aligned.m8n8.x4.shared.b16 {%0,%1,%2,%3}, [%4];"
        : "=r"(r[0]), "=r"(r[1]), "=r"(r[2]), "=r"(r[3]) : "r"(addr));
}
__device__ __forceinline__ void ldsm_x4t(uint32_t r[4], uint32_t addr) {
    asm volatile("ldmatrix.sync.aligned.m8n8.x4.trans.shared.b16 {%0,%1,%2,%3}, [%4];"
        : "=r"(r[0]), "=r"(r[1]), "=r"(r[2]), "=r"(r[3]) : "r"(addr));
}

// ---------------- 1) router GEMM ----------------
__global__ void router_gemm(const float* __restrict__ x, const float* __restrict__ rw) {
    __shared__ float As[32][33];
    __shared__ float Bs[32][65];
    const int tid = threadIdx.x;
    const int t0  = blockIdx.x * 32;
    const int m   = tid >> 3, nb = tid & 7;
    float acc[8] = {};
    for (int kt = 0; kt < HID; kt += 32) {
        __syncthreads();
        {   int r = tid >> 3, c = (tid & 7) * 4;
            const float4 v = *(const float4*)(x + (size_t)(t0 + r)*HID + kt + c);
            As[r][c] = v.x; As[r][c+1] = v.y; As[r][c+2] = v.z; As[r][c+3] = v.w; }
        #pragma unroll
        for (int i = 0; i < 8; i++) {
            int idx = tid + i*256; int e = idx >> 5, k = idx & 31;
            Bs[k][e] = rw[(size_t)e*HID + kt + k];
        }
        __syncthreads();
        #pragma unroll
        for (int k = 0; k < 32; k++) {
            float a = As[m][k];
            #pragma unroll
            for (int j = 0; j < 8; j++) acc[j] += a * Bs[k][nb + 8*j];
        }
    }
    #pragma unroll
    for (int j = 0; j < 8; j++) g_logits[(size_t)(t0+m)*NEXP + nb + 8*j] = acc[j];
}

// ---------------- 2) top-k ----------------
__global__ void zero_cnt_kernel() { if (threadIdx.x < NEXP) g_cnt[threadIdx.x] = 0; }

__global__ void topk_kernel() {
    int t = blockIdx.x * blockDim.x + threadIdx.x;
    if (t >= T_TOK) return;
    float l[NEXP];
    #pragma unroll
    for (int e = 0; e < NEXP; e++) l[e] = g_logits[(size_t)t*NEXP + e];
    float bw[TOPK]; int bi[TOPK];
    for (int i = 0; i < TOPK; i++) {
        float mv = -1e30f; int mi = 0;
        for (int e = 0; e < NEXP; e++) if (l[e] > mv) { mv = l[e]; mi = e; }
        bw[i] = mv; bi[i] = mi; l[mi] = -1e30f;
    }
    float s = 0.f, mx = bw[0], w[TOPK];
    #pragma unroll
    for (int i = 0; i < TOPK; i++) { w[i] = expf(bw[i] - mx); s += w[i]; }
    float inv = 1.f / s;
    #pragma unroll
    for (int i = 0; i < TOPK; i++) {
        g_sel [t*TOPK+i] = bi[i];
        g_selw[t*TOPK+i] = w[i]*inv;
        atomicAdd(&g_cnt[bi[i]], 1);
    }
}

// ---------------- 3) prefix scan + scatter ----------------
__global__ void scan_kernel() {
    const int i = threadIdx.x;
    __shared__ int tmp[NEXP];
    int v = g_cnt[i];
    tmp[i] = v;
    __syncthreads();
    #pragma unroll
    for (int d = 1; d < NEXP; d <<= 1) {
        int o = (i >= d) ? tmp[i-d] : 0;
        __syncthreads();
        tmp[i] += o;
        __syncthreads();
    }
    int excl = tmp[i] - v;
    g_off[i] = excl; g_cur[i] = excl;
}
__global__ void scatter_kernel() {
    int idx = blockIdx.x*blockDim.x + threadIdx.x;
    if (idx >= T_TOK*TOPK) return;
    int t = idx >> 3;
    int e = g_sel[idx];
    int pos = atomicAdd(&g_cur[e], 1);
    g_tok[pos] = t; g_tw[pos] = g_selw[idx]; g_rowof[idx] = pos;
}

// ---------------- 4) stage 1 (fp16 mma + ldmatrix, K-tile=64) --------------
// grid (16, 66, 8); M=128, N=64 gate + 64 up, 512 threads
#define S1_A    1024
#define S1_BG   (S1_A  + 2*128*SA*2)
#define S1_BU   (S1_BG + 2*64*SB1*2)
#define S1_SMEM (S1_BU + 2*64*SB1*2)
__global__ void __launch_bounds__(512, 1)
stage1_kernel(const float* __restrict__ x,
              const float* __restrict__ wg_,
              const float* __restrict__ wu_,
              const float* __restrict__ sg_,
              const float* __restrict__ su_) {
    const int s = blockIdx.y;
    int nrows, hbase, ldb, offmoe = 0;
    const float *Bg, *Bu;
    if (s < 2) {
        nrows = T_TOK; hbase = s*T_TOK; ldb = SINTER;
        Bg = sg_ + s*INTER; Bu = su_ + s*INTER;
    } else {
        int e = s - 2;
        nrows = g_cnt[e]; offmoe = g_off[e]; hbase = ROWS_SHARED + offmoe; ldb = INTER;
        Bg = wg_ + (size_t)e*HID*INTER; Bu = wu_ + (size_t)e*HID*INTER;
    }
    const int m0 = blockIdx.x * 128;
    if (m0 >= nrows) return;
    const int n0   = blockIdx.z * 64;
    const int nloc = nrows - m0;

    extern __shared__ char smraw[];
    int*    s_tok = (int*)smraw;
    float*  s_w   = (float*)(smraw + 512);
    __half* Ash   = (__half*)(smraw + S1_A);
    __half* Bgs   = (__half*)(smraw + S1_BG);
    __half* Bus   = (__half*)(smraw + S1_BU);
    const uint32_t aB  = smem_u32(Ash);
    const uint32_t bgB = smem_u32(Bgs);
    const uint32_t buB = smem_u32(Bus);

    const int tid = threadIdx.x;
    if (tid < 128) {
        int r = m0 + tid;
        if (r < nrows) {
            if (s < 2) { s_tok[tid] = r; s_w[tid] = 1.f; }
            else       { s_tok[tid] = g_tok[offmoe + r]; s_w[tid] = g_tw[offmoe + r]; }
        } else { s_tok[tid] = (s < 2) ? 0 : g_tok[offmoe]; s_w[tid] = 0.f; }
    }
    __syncthreads();

    const int lane = tid & 31, warp = tid >> 5;
    const int wm = warp >> 2, wn = warp & 3;      // 4x4 warps: 32m x 16n
    const int l4 = lane >> 2, lq = lane & 3;
    const int lr = lane & 15, lc = lane >> 4;
    float cg[2][2][4] = {}, cu[2][2][4] = {};

    // ldmatrix base offsets (bytes)
    const uint32_t aFrag = aB  + (uint32_t)(wm*32 + lr)*(SA*2) + lc*16;
    const uint32_t gFrag = bgB + (uint32_t)lr*(SB1*2) + wn*32 + lc*16;
    const uint32_t uFrag = buB + (uint32_t)lr*(SB1*2) + wn*32 + lc*16;

    // staging geometry: A rows (tid>>4)+i*32, col (tid&15)*4 ; B rows (tid>>4)+i*32
    const int arow = tid >> 4, acol = (tid & 15) << 2;
    const float* ap[4];
    #pragma unroll
    for (int i = 0; i < 4; i++) ap[i] = x + (size_t)s_tok[arow + i*32]*HID + acol;
    const float* bgp[2]; const float* bup[2];
    #pragma unroll
    for (int i = 0; i < 2; i++) {
        bgp[i] = Bg + (size_t)(arow + i*32)*ldb + n0 + acol;
        bup[i] = Bu + (size_t)(arow + i*32)*ldb + n0 + acol;
    }

    float4 ra[4], rg[2], ru[2];
    auto loadT = [&](int kt) {
        #pragma unroll
        for (int i = 0; i < 4; i++) ra[i] = *(const float4*)(ap[i] + kt);
        #pragma unroll
        for (int i = 0; i < 2; i++) {
            rg[i] = *(const float4*)(bgp[i] + (size_t)kt*ldb);
            ru[i] = *(const float4*)(bup[i] + (size_t)kt*ldb);
        }
    };
    auto storeT = [&](int buf) {
        #pragma unroll
        for (int i = 0; i < 4; i++)
            *(uint2*)(Ash + (buf*128 + arow + i*32)*SA + acol) =
                make_uint2(packh2(ra[i].x, ra[i].y), packh2(ra[i].z, ra[i].w));
        #pragma unroll
        for (int i = 0; i < 2; i++) {
            *(uint2*)(Bgs + (buf*64 + arow + i*32)*SB1 + acol) =
                make_uint2(packh2(rg[i].x, rg[i].y), packh2(rg[i].z, rg[i].w));
            *(uint2*)(Bus + (buf*64 + arow + i*32)*SB1 + acol) =
                make_uint2(packh2(ru[i].x, ru[i].y), packh2(ru[i].z, ru[i].w));
        }
    };
    auto comp = [&](int buf) {
        const uint32_t aOff = aFrag + (uint32_t)buf*(128*SA*2);
        const uint32_t gOff = gFrag + (uint32_t)buf*(64*SB1*2);
        const uint32_t uOff = uFrag + (uint32_t)buf*(64*SB1*2);
        #pragma unroll
        for (int ks = 0; ks < 4; ks++) {          // four k16 steps cover K=64
            uint32_t a0[4], a1[4], bg[4], bu[4];
            ldsm_x4 (a0, aOff + ks*32);
            ldsm_x4 (a1, aOff + 16*(SA*2) + ks*32);
            ldsm_x4t(bg, gOff + ks*16*(SB1*2));
            ldsm_x4t(bu, uOff + ks*16*(SB1*2));
            #pragma unroll
            for (int ni = 0; ni < 2; ni++) {
                mma16(cg[0][ni], a0, bg[2*ni], bg[2*ni+1]);
                mma16(cg[1][ni], a1, bg[2*ni], bg[2*ni+1]);
                mma16(cu[0][ni], a0, bu[2*ni], bu[2*ni+1]);
                mma16(cu[1][ni], a1, bu[2*ni], bu[2*ni+1]);
            }
        }
    };

    loadT(0); storeT(0); __syncthreads();
    const int NT = HID / 64;
    #pragma unroll 1
    for (int it = 0; it < NT; it++) {
        int buf = it & 1;
        if (it + 1 < NT) loadT((it + 1) * 64);
        comp(buf);
        if (it + 1 < NT) { storeT(buf ^ 1); __syncthreads(); }
    }

    #pragma unroll
    for (int mi = 0; mi < 2; mi++)
        #pragma unroll
        for (int ni = 0; ni < 2; ni++)
            #pragma unroll
            for (int j = 0; j < 4; j++) {
                int r = wm*32 + mi*16 + l4 + ((j >> 1) << 3);
                int c = wn*16 + ni*8 + 2*lq + (j & 1);
                if (r < nloc) {
                    float g = cg[mi][ni][j], u = cu[mi][ni][j];
                    float h = g / (1.f + __expf(-g)) * u * s_w[r];
                    g_H[(size_t)(hbase + m0 + r)*INTER + n0 + c] = h;
                }
            }
}

// ---------------- 5) stage 2 (fp16 mma + ldmatrix, K-tile=64) --------------
// grid (16, 66, 16); M=128, N=128, 512 threads
#define S2_B    (2*128*SA*2)
#define S2_SMEM (S2_B + 2*64*SB2*2)
__global__ void __launch_bounds__(512, 1)
stage2_kernel(const float* __restrict__ wd_,
              const float* __restrict__ sd_) {
    const int s = blockIdx.y;
    int nrows, hbase; const float* Bd;
    if (s < 2) { nrows = T_TOK; hbase = s*T_TOK; Bd = sd_ + (size_t)s*INTER*HID; }
    else { int e = s-2; nrows = g_cnt[e]; hbase = ROWS_SHARED + g_off[e];
           Bd = wd_ + (size_t)e*INTER*HID; }
    const int m0 = blockIdx.x * 128;
    if (m0 >= nrows) return;
    const int n0   = blockIdx.z * 128;
    const int nloc = nrows - m0;

    extern __shared__ char smraw[];
    __half* Ash = (__half*)smraw;
    __half* Bsh = (__half*)(smraw + S2_B);
    const uint32_t aB = smem_u32(Ash);
    const uint32_t bB = smem_u32(Bsh);

    const int tid = threadIdx.x, lane = tid & 31, warp = tid >> 5;
    const int wm = warp >> 2, wn = warp & 3;    // 4x4: 32m x 32n per warp
    const int l4 = lane >> 2, lq = lane & 3;
    const int lr = lane & 15, lc = lane >> 4;
    float cc[2][4][4] = {};

    const uint32_t aFrag = aB + (uint32_t)(wm*32 + lr)*(SA*2) + lc*16;
    const uint32_t bFrag = bB + (uint32_t)lr*(SB2*2) + wn*64 + lc*16;

    // staging: A rows (tid>>4)+i*32 col (tid&15)*4 ; B rows (tid>>5)+i*16 col (tid&31)*4
    const int arow = tid >> 4, acol = (tid & 15) << 2;
    const int brow = tid >> 5, bcol = (tid & 31) << 2;
    const float* ap[4];
    #pragma unroll
    for (int i = 0; i < 4; i++) {
        int r = arow + i*32;
        int rr = (r < nloc) ? r : 0;
        ap[i] = g_H + (size_t)(hbase + m0 + rr)*INTER + acol;
    }
    const float* bp[4];
    #pragma unroll
    for (int i = 0; i < 4; i++) bp[i] = Bd + (size_t)(brow + i*16)*HID + n0 + bcol;

    float4 ra[4], rb[4];
    auto loadT = [&](int kt) {
        #pragma unroll
        for (int i = 0; i < 4; i++) ra[i] = *(const float4*)(ap[i] + kt);
        #pragma unroll
        for (int i = 0; i < 4; i++) rb[i] = *(const float4*)(bp[i] + (size_t)kt*HID);
    };
    auto storeT = [&](int buf) {
        #pragma unroll
        for (int i = 0; i < 4; i++)
            *(uint2*)(Ash + (buf*128 + arow + i*32)*SA + acol) =
                make_uint2(packh2(ra[i].x, ra[i].y), packh2(ra[i].z, ra[i].w));
        #pragma unroll
        for (int i = 0; i < 4; i++)
            *(uint2*)(Bsh + (buf*64 + brow + i*16)*SB2 + bcol) =
                make_uint2(packh2(rb[i].x, rb[i].y), packh2(rb[i].z, rb[i].w));
    };
    auto comp = [&](int buf) {
        const uint32_t aOff = aFrag + (uint32_t)buf*(128*SA*2);
        const uint32_t bOff = bFrag + (uint32_t)buf*(64*SB2*2);
        #pragma unroll
        for (int ks = 0; ks < 4; ks++) {
            uint32_t a0[4], a1[4], b0[4], b1[4];
            ldsm_x4 (a0, aOff + ks*32);
            ldsm_x4 (a1, aOff + 16*(SA*2) + ks*32);
            ldsm_x4t(b0, bOff + ks*16*(SB2*2));
            ldsm_x4t(b1, bOff + ks*16*(SB2*2) + 32);
            #pragma unroll
            for (int p = 0; p < 2; p++) {
                const uint32_t* bpp = p ? b1 : b0;
                #pragma unroll
                for (int q = 0; q < 2; q++) {
                    mma16(cc[0][p*2+q], a0, bpp[2*q], bpp[2*q+1]);
                    mma16(cc[1][p*2+q], a1, bpp[2*q], bpp[2*q+1]);
                }
            }
        }
    };

    loadT(0); storeT(0); __syncthreads();
    const int NT = INTER / 64;
    #pragma unroll 1
    for (int it = 0; it < NT; it++) {
        int buf = it & 1;
        if (it + 1 < NT) loadT((it + 1) * 64);
        comp(buf);
        if (it + 1 < NT) { storeT(buf ^ 1); __syncthreads(); }
    }

    #pragma unroll
    for (int mi = 0; mi < 2; mi++)
        #pragma unroll
        for (int ni = 0; ni < 4; ni++) {
            int r0 = wm*32 + mi*16 + l4;
            int c0 = wn*32 + ni*8 + 2*lq;
            if (r0 < nloc)
                *(float2*)(g_Y + (size_t)(hbase+m0+r0)*HID + n0 + c0) =
                    make_float2(cc[mi][ni][0], cc[mi][ni][1]);
            int r1 = r0 + 8;
            if (r1 < nloc)
                *(float2*)(g_Y + (size_t)(hbase+m0+r1)*HID + n0 + c0) =
                    make_float2(cc[mi][ni][2], cc[mi][ni][3]);
        }
}

// ---------------- 6) combine ----------------
__global__ void combine_kernel(float* __restrict__ out) {
    const int t = blockIdx.x;
    __shared__ int rows[10];
    const int tid = threadIdx.x;
    if (tid < 8)       rows[tid] = ROWS_SHARED + g_rowof[t*TOPK + tid];
    else if (tid == 8) rows[8] = t;
    else if (tid == 9) rows[9] = T_TOK + t;
    __syncthreads();
    for (int c = tid*4; c < HID; c += 1024) {
        float4 acc = make_float4(0.f,0.f,0.f,0.f);
        #pragma unroll
        for (int j = 0; j < 10; j++) {
            const float4 v = *(const float4*)(g_Y + (size_t)rows[j]*HID + c);
            acc.x += v.x; acc.y += v.y; acc.z += v.z; acc.w += v.w;
        }
        *(float4*)(out + (size_t)t*HID + c) = acc;
    }
}

// ---------------- launch ----------------
extern "C" void kernel_launch(void* const* d_in, const int* in_sizes, int n_in,
                              void* d_out, int out_size) {
    const float* x  = (const float*)d_in[0];
    const float* rw = (const float*)d_in[1];
    const float* wg = (const float*)d_in[2];
    const float* wu = (const float*)d_in[3];
    const float* wd = (const float*)d_in[4];
    const float* sg = (const float*)d_in[5];
    const float* su = (const float*)d_in[6];
    const float* sd = (const float*)d_in[7];
    float* out = (float*)d_out;

    static bool attr_done = false;
    if (!attr_done) {
        cudaFuncSetAttribute(stage1_kernel, cudaFuncAttributeMaxDynamicSharedMemorySize, S1_SMEM);
        cudaFuncSetAttribute(stage2_kernel, cudaFuncAttributeMaxDynamicSharedMemorySize, S2_SMEM);
        attr_done = true;
    }

    router_gemm   <<<64, 256>>>(x, rw);
    zero_cnt_kernel<<<1, 64>>>();
    topk_kernel   <<<8, 256>>>();
    scan_kernel   <<<1, 64>>>();
    scatter_kernel<<<64, 256>>>();
    stage1_kernel <<<dim3(16, 66, 8),  512, S1_SMEM>>>(x, wg, wu, sg, su);
    stage2_kernel <<<dim3(16, 66, 16), 512, S2_SMEM>>>(wd, sd);
    combine_kernel<<<2048, 256>>>(out);
}

// round 7
// speedup vs baseline: 2.9531x; 1.0184x over previous
#include <cuda_runtime.h>
#include <cuda_fp16.h>
#include <cstdint>

#define T_TOK   2048
#define HID     2048
#define NEXP    64
#define INTER   512
#define SINTER  1024
#define TOPK    8
#define ROWS_SHARED 4096
#define ROWS_MOE    (T_TOK*TOPK)
#define ROWS_TOTAL  (ROWS_SHARED + ROWS_MOE)

#define SA   72   // A smem row stride (halves): K=64 + pad 8
#define SB1  72   // stage1 B row stride (halves): N=64 + pad 8
#define SB2  136  // stage2 B row stride (halves): N=128 + pad 8

// ---------------- device scratch ----------------
__device__ float    g_logits[T_TOK*NEXP];
__device__ int      g_sel  [T_TOK*TOPK];
__device__ float    g_selw [T_TOK*TOPK];
__device__ int      g_cnt  [NEXP];
__device__ int      g_off  [NEXP];
__device__ int      g_cur  [NEXP];
__device__ int      g_tok  [ROWS_MOE];
__device__ float    g_tw   [ROWS_MOE];
__device__ __half   g_Hh[(size_t)ROWS_TOTAL*INTER];   // fp16 intermediate (21 MB)

// ---------------- helpers ----------------
__device__ __forceinline__ uint32_t smem_u32(const void* p) {
    uint32_t a;
    asm("{ .reg .u64 t; cvta.to.shared.u64 t, %1; cvt.u32.u64 %0, t; }" : "=r"(a) : "l"(p));
    return a;
}
__device__ __forceinline__ uint32_t packh2(float x, float y) {
    __half2 h = __floats2half2_rn(x, y);
    return *(uint32_t*)&h;
}
__device__ __forceinline__ void mma16(float c[4], const uint32_t a[4],
                                      uint32_t b0, uint32_t b1) {
    asm volatile(
        "mma.sync.aligned.m16n8k16.row.col.f32.f16.f16.f32 "
        "{%0,%1,%2,%3}, {%4,%5,%6,%7}, {%8,%9}, {%0,%1,%2,%3};\n"
        : "+f"(c[0]), "+f"(c[1]), "+f"(c[2]), "+f"(c[3])
        : "r"(a[0]), "r"(a[1]), "r"(a[2]), "r"(a[3]), "r"(b0), "r"(b1));
}
__device__ __forceinline__ void ldsm_x4(uint32_t r[4], uint32_t addr) {
    asm volatile("ldmatrix.sync.aligned.m8n8.x4.shared.b16 {%0,%1,%2,%3}, [%4];"
        : "=r"(r[0]), "=r"(r[1]), "=r"(r[2]), "=r"(r[3]) : "r"(addr));
}
__device__ __forceinline__ void ldsm_x4t(uint32_t r[4], uint32_t addr) {
    asm volatile("ldmatrix.sync.aligned.m8n8.x4.trans.shared.b16 {%0,%1,%2,%3}, [%4];"
        : "=r"(r[0]), "=r"(r[1]), "=r"(r[2]), "=r"(r[3]) : "r"(addr));
}
__device__ __forceinline__ void red_add_v2(float* p, float a, float b) {
    asm volatile("red.global.add.v2.f32 [%0], {%1, %2};"
        :: "l"(p), "f"(a), "f"(b) : "memory");
}

// ---------------- 0) zero output ----------------
__global__ void zero_out_kernel(float4* __restrict__ out4) {
    int i = blockIdx.x*blockDim.x + threadIdx.x;
    if (i < T_TOK*HID/4) out4[i] = make_float4(0.f,0.f,0.f,0.f);
}

// ---------------- 1) router GEMM ----------------
__global__ void router_gemm(const float* __restrict__ x, const float* __restrict__ rw) {
    __shared__ float As[32][33];
    __shared__ float Bs[32][65];
    const int tid = threadIdx.x;
    const int t0  = blockIdx.x * 32;
    const int m   = tid >> 3, nb = tid & 7;
    float acc[8] = {};
    for (int kt = 0; kt < HID; kt += 32) {
        __syncthreads();
        {   int r = tid >> 3, c = (tid & 7) * 4;
            const float4 v = *(const float4*)(x + (size_t)(t0 + r)*HID + kt + c);
            As[r][c] = v.x; As[r][c+1] = v.y; As[r][c+2] = v.z; As[r][c+3] = v.w; }
        #pragma unroll
        for (int i = 0; i < 8; i++) {
            int idx = tid + i*256; int e = idx >> 5, k = idx & 31;
            Bs[k][e] = rw[(size_t)e*HID + kt + k];
        }
        __syncthreads();
        #pragma unroll
        for (int k = 0; k < 32; k++) {
            float a = As[m][k];
            #pragma unroll
            for (int j = 0; j < 8; j++) acc[j] += a * Bs[k][nb + 8*j];
        }
    }
    #pragma unroll
    for (int j = 0; j < 8; j++) g_logits[(size_t)(t0+m)*NEXP + nb + 8*j] = acc[j];
}

// ---------------- 2) top-k ----------------
__global__ void zero_cnt_kernel() { if (threadIdx.x < NEXP) g_cnt[threadIdx.x] = 0; }

__global__ void topk_kernel() {
    int t = blockIdx.x * blockDim.x + threadIdx.x;
    if (t >= T_TOK) return;
    float l[NEXP];
    #pragma unroll
    for (int e = 0; e < NEXP; e++) l[e] = g_logits[(size_t)t*NEXP + e];
    float bw[TOPK]; int bi[TOPK];
    for (int i = 0; i < TOPK; i++) {
        float mv = -1e30f; int mi = 0;
        for (int e = 0; e < NEXP; e++) if (l[e] > mv) { mv = l[e]; mi = e; }
        bw[i] = mv; bi[i] = mi; l[mi] = -1e30f;
    }
    float s = 0.f, mx = bw[0], w[TOPK];
    #pragma unroll
    for (int i = 0; i < TOPK; i++) { w[i] = expf(bw[i] - mx); s += w[i]; }
    float inv = 1.f / s;
    #pragma unroll
    for (int i = 0; i < TOPK; i++) {
        g_sel [t*TOPK+i] = bi[i];
        g_selw[t*TOPK+i] = w[i]*inv;
        atomicAdd(&g_cnt[bi[i]], 1);
    }
}

// ---------------- 3) prefix scan + scatter ----------------
__global__ void scan_kernel() {
    const int i = threadIdx.x;
    __shared__ int tmp[NEXP];
    int v = g_cnt[i];
    tmp[i] = v;
    __syncthreads();
    #pragma unroll
    for (int d = 1; d < NEXP; d <<= 1) {
        int o = (i >= d) ? tmp[i-d] : 0;
        __syncthreads();
        tmp[i] += o;
        __syncthreads();
    }
    int excl = tmp[i] - v;
    g_off[i] = excl; g_cur[i] = excl;
}
__global__ void scatter_kernel() {
    int idx = blockIdx.x*blockDim.x + threadIdx.x;
    if (idx >= T_TOK*TOPK) return;
    int t = idx >> 3;
    int e = g_sel[idx];
    int pos = atomicAdd(&g_cur[e], 1);
    g_tok[pos] = t; g_tw[pos] = g_selw[idx];
}

// ---------------- 4) stage 1 (fp16 mma + ldmatrix, K-tile=64) --------------
// grid (16, 66, 8); M=128, N=64 gate + 64 up, 512 threads
#define S1_A    1024
#define S1_BG   (S1_A  + 2*128*SA*2)
#define S1_BU   (S1_BG + 2*64*SB1*2)
#define S1_SMEM (S1_BU + 2*64*SB1*2)
__global__ void __launch_bounds__(512, 1)
stage1_kernel(const float* __restrict__ x,
              const float* __restrict__ wg_,
              const float* __restrict__ wu_,
              const float* __restrict__ sg_,
              const float* __restrict__ su_) {
    const int s = blockIdx.y;
    int nrows, hbase, ldb, offmoe = 0;
    const float *Bg, *Bu;
    if (s < 2) {
        nrows = T_TOK; hbase = s*T_TOK; ldb = SINTER;
        Bg = sg_ + s*INTER; Bu = su_ + s*INTER;
    } else {
        int e = s - 2;
        nrows = g_cnt[e]; offmoe = g_off[e]; hbase = ROWS_SHARED + offmoe; ldb = INTER;
        Bg = wg_ + (size_t)e*HID*INTER; Bu = wu_ + (size_t)e*HID*INTER;
    }
    const int m0 = blockIdx.x * 128;
    if (m0 >= nrows) return;
    const int n0   = blockIdx.z * 64;
    const int nloc = nrows - m0;

    extern __shared__ char smraw[];
    int*    s_tok = (int*)smraw;
    float*  s_w   = (float*)(smraw + 512);
    __half* Ash   = (__half*)(smraw + S1_A);
    __half* Bgs   = (__half*)(smraw + S1_BG);
    __half* Bus   = (__half*)(smraw + S1_BU);
    const uint32_t aB  = smem_u32(Ash);
    const uint32_t bgB = smem_u32(Bgs);
    const uint32_t buB = smem_u32(Bus);

    const int tid = threadIdx.x;
    if (tid < 128) {
        int r = m0 + tid;
        if (r < nrows) {
            if (s < 2) { s_tok[tid] = r; s_w[tid] = 1.f; }
            else       { s_tok[tid] = g_tok[offmoe + r]; s_w[tid] = g_tw[offmoe + r]; }
        } else { s_tok[tid] = (s < 2) ? 0 : g_tok[offmoe]; s_w[tid] = 0.f; }
    }
    __syncthreads();

    const int lane = tid & 31, warp = tid >> 5;
    const int wm = warp >> 2, wn = warp & 3;      // 4x4 warps: 32m x 16n
    const int l4 = lane >> 2, lq = lane & 3;
    const int lr = lane & 15, lc = lane >> 4;
    float cg[2][2][4] = {}, cu[2][2][4] = {};

    const uint32_t aFrag = aB  + (uint32_t)(wm*32 + lr)*(SA*2) + lc*16;
    const uint32_t gFrag = bgB + (uint32_t)lr*(SB1*2) + wn*32 + lc*16;
    const uint32_t uFrag = buB + (uint32_t)lr*(SB1*2) + wn*32 + lc*16;

    const int arow = tid >> 4, acol = (tid & 15) << 2;
    const float* ap[4];
    #pragma unroll
    for (int i = 0; i < 4; i++) ap[i] = x + (size_t)s_tok[arow + i*32]*HID + acol;
    const float* bgp[2]; const float* bup[2];
    #pragma unroll
    for (int i = 0; i < 2; i++) {
        bgp[i] = Bg + (size_t)(arow + i*32)*ldb + n0 + acol;
        bup[i] = Bu + (size_t)(arow + i*32)*ldb + n0 + acol;
    }

    float4 ra[4], rg[2], ru[2];
    auto loadT = [&](int kt) {
        #pragma unroll
        for (int i = 0; i < 4; i++) ra[i] = *(const float4*)(ap[i] + kt);
        #pragma unroll
        for (int i = 0; i < 2; i++) {
            rg[i] = *(const float4*)(bgp[i] + (size_t)kt*ldb);
            ru[i] = *(const float4*)(bup[i] + (size_t)kt*ldb);
        }
    };
    auto storeT = [&](int buf) {
        #pragma unroll
        for (int i = 0; i < 4; i++)
            *(uint2*)(Ash + (buf*128 + arow + i*32)*SA + acol) =
                make_uint2(packh2(ra[i].x, ra[i].y), packh2(ra[i].z, ra[i].w));
        #pragma unroll
        for (int i = 0; i < 2; i++) {
            *(uint2*)(Bgs + (buf*64 + arow + i*32)*SB1 + acol) =
                make_uint2(packh2(rg[i].x, rg[i].y), packh2(rg[i].z, rg[i].w));
            *(uint2*)(Bus + (buf*64 + arow + i*32)*SB1 + acol) =
                make_uint2(packh2(ru[i].x, ru[i].y), packh2(ru[i].z, ru[i].w));
        }
    };
    auto comp = [&](int buf) {
        const uint32_t aOff = aFrag + (uint32_t)buf*(128*SA*2);
        const uint32_t gOff = gFrag + (uint32_t)buf*(64*SB1*2);
        const uint32_t uOff = uFrag + (uint32_t)buf*(64*SB1*2);
        #pragma unroll
        for (int ks = 0; ks < 4; ks++) {
            uint32_t a0[4], a1[4], bg[4], bu[4];
            ldsm_x4 (a0, aOff + ks*32);
            ldsm_x4 (a1, aOff + 16*(SA*2) + ks*32);
            ldsm_x4t(bg, gOff + ks*16*(SB1*2));
            ldsm_x4t(bu, uOff + ks*16*(SB1*2));
            #pragma unroll
            for (int ni = 0; ni < 2; ni++) {
                mma16(cg[0][ni], a0, bg[2*ni], bg[2*ni+1]);
                mma16(cg[1][ni], a1, bg[2*ni], bg[2*ni+1]);
                mma16(cu[0][ni], a0, bu[2*ni], bu[2*ni+1]);
                mma16(cu[1][ni], a1, bu[2*ni], bu[2*ni+1]);
            }
        }
    };

    loadT(0); storeT(0); __syncthreads();
    const int NT = HID / 64;
    #pragma unroll 1
    for (int it = 0; it < NT; it++) {
        int buf = it & 1;
        if (it + 1 < NT) loadT((it + 1) * 64);
        comp(buf);
        if (it + 1 < NT) { storeT(buf ^ 1); __syncthreads(); }
    }

    // epilogue -> fp16 H
    #pragma unroll
    for (int mi = 0; mi < 2; mi++)
        #pragma unroll
        for (int ni = 0; ni < 2; ni++) {
            int c0 = wn*16 + ni*8 + 2*lq;
            int r0 = wm*32 + mi*16 + l4;
            float w0 = (r0 < nloc) ? s_w[r0] : 0.f;
            if (r0 < nloc) {
                float g0 = cg[mi][ni][0], u0 = cu[mi][ni][0];
                float g1 = cg[mi][ni][1], u1 = cu[mi][ni][1];
                float h0 = g0 / (1.f + __expf(-g0)) * u0 * w0;
                float h1 = g1 / (1.f + __expf(-g1)) * u1 * w0;
                *(uint32_t*)(g_Hh + (size_t)(hbase + m0 + r0)*INTER + n0 + c0) = packh2(h0, h1);
            }
            int r1 = r0 + 8;
            if (r1 < nloc) {
                float w1 = s_w[r1];
                float g2 = cg[mi][ni][2], u2 = cu[mi][ni][2];
                float g3 = cg[mi][ni][3], u3 = cu[mi][ni][3];
                float h2 = g2 / (1.f + __expf(-g2)) * u2 * w1;
                float h3 = g3 / (1.f + __expf(-g3)) * u3 * w1;
                *(uint32_t*)(g_Hh + (size_t)(hbase + m0 + r1)*INTER + n0 + c0) = packh2(h2, h3);
            }
        }
}

// ---------------- 5) stage 2 (fp16 mma, fused combine via red.add) ---------
// grid (16, 66, 16); M=128, N=128, 512 threads
#define S2_B    (2*128*SA*2)
#define S2_TOK  (S2_B + 2*64*SB2*2)
#define S2_SMEM (S2_TOK + 512)
__global__ void __launch_bounds__(512, 1)
stage2_kernel(const float* __restrict__ wd_,
              const float* __restrict__ sd_,
              float* __restrict__ out) {
    const int s = blockIdx.y;
    int nrows, hbase, offmoe = 0; const float* Bd;
    if (s < 2) { nrows = T_TOK; hbase = s*T_TOK; Bd = sd_ + (size_t)s*INTER*HID; }
    else { int e = s-2; nrows = g_cnt[e]; offmoe = g_off[e]; hbase = ROWS_SHARED + offmoe;
           Bd = wd_ + (size_t)e*INTER*HID; }
    const int m0 = blockIdx.x * 128;
    if (m0 >= nrows) return;
    const int n0   = blockIdx.z * 128;
    const int nloc = nrows - m0;

    extern __shared__ char smraw[];
    __half* Ash = (__half*)smraw;
    __half* Bsh = (__half*)(smraw + S2_B);
    int*    s_tok = (int*)(smraw + S2_TOK);
    const uint32_t aB = smem_u32(Ash);
    const uint32_t bB = smem_u32(Bsh);

    const int tid = threadIdx.x, lane = tid & 31, warp = tid >> 5;
    if (tid < 128) {
        int r = m0 + tid;
        if (r < nrows) s_tok[tid] = (s < 2) ? r : g_tok[offmoe + r];
        else           s_tok[tid] = 0;
    }
    __syncthreads();

    const int wm = warp >> 2, wn = warp & 3;    // 4x4: 32m x 32n per warp
    const int l4 = lane >> 2, lq = lane & 3;
    const int lr = lane & 15, lc = lane >> 4;
    float cc[2][4][4] = {};

    const uint32_t aFrag = aB + (uint32_t)(wm*32 + lr)*(SA*2) + lc*16;
    const uint32_t bFrag = bB + (uint32_t)lr*(SB2*2) + wn*64 + lc*16;

    // A staging: fp16 rows, thread covers row tid>>2, 16 halves at (tid&3)*16
    const int arow = tid >> 2, acol = (tid & 3) << 4;
    const int brow = tid >> 5, bcol = (tid & 31) << 2;
    const __half* ahp;
    {
        int rr = (arow < nloc) ? arow : 0;
        ahp = g_Hh + (size_t)(hbase + m0 + rr)*INTER + acol;
    }
    const float* bp[4];
    #pragma unroll
    for (int i = 0; i < 4; i++) bp[i] = Bd + (size_t)(brow + i*16)*HID + n0 + bcol;

    uint4 ra[2]; float4 rb[4];
    auto loadT = [&](int kt) {
        ra[0] = *(const uint4*)(ahp + kt);
        ra[1] = *(const uint4*)(ahp + kt + 8);
        #pragma unroll
        for (int i = 0; i < 4; i++) rb[i] = *(const float4*)(bp[i] + (size_t)kt*HID);
    };
    auto storeT = [&](int buf) {
        *(uint4*)(Ash + (buf*128 + arow)*SA + acol)     = ra[0];
        *(uint4*)(Ash + (buf*128 + arow)*SA + acol + 8) = ra[1];
        #pragma unroll
        for (int i = 0; i < 4; i++)
            *(uint2*)(Bsh + (buf*64 + brow + i*16)*SB2 + bcol) =
                make_uint2(packh2(rb[i].x, rb[i].y), packh2(rb[i].z, rb[i].w));
    };
    auto comp = [&](int buf) {
        const uint32_t aOff = aFrag + (uint32_t)buf*(128*SA*2);
        const uint32_t bOff = bFrag + (uint32_t)buf*(64*SB2*2);
        #pragma unroll
        for (int ks = 0; ks < 4; ks++) {
            uint32_t a0[4], a1[4], b0[4], b1[4];
            ldsm_x4 (a0, aOff + ks*32);
            ldsm_x4 (a1, aOff + 16*(SA*2) + ks*32);
            ldsm_x4t(b0, bOff + ks*16*(SB2*2));
            ldsm_x4t(b1, bOff + ks*16*(SB2*2) + 32);
            #pragma unroll
            for (int p = 0; p < 2; p++) {
                const uint32_t* bpp = p ? b1 : b0;
                #pragma unroll
                for (int q = 0; q < 2; q++) {
                    mma16(cc[0][p*2+q], a0, bpp[2*q], bpp[2*q+1]);
                    mma16(cc[1][p*2+q], a1, bpp[2*q], bpp[2*q+1]);
                }
            }
        }
    };

    loadT(0); storeT(0); __syncthreads();
    const int NT = INTER / 64;
    #pragma unroll 1
    for (int it = 0; it < NT; it++) {
        int buf = it & 1;
        if (it + 1 < NT) loadT((it + 1) * 64);
        comp(buf);
        if (it + 1 < NT) { storeT(buf ^ 1); __syncthreads(); }
    }

    // fused combine: reduce into out[token, n]
    #pragma unroll
    for (int mi = 0; mi < 2; mi++) {
        int r0 = wm*32 + mi*16 + l4;
        int r1 = r0 + 8;
        int tk0 = s_tok[r0], tk1 = s_tok[r1 & 127];
        #pragma unroll
        for (int ni = 0; ni < 4; ni++) {
            int c0 = n0 + wn*32 + ni*8 + 2*lq;
            if (r0 < nloc)
                red_add_v2(out + (size_t)tk0*HID + c0, cc[mi][ni][0], cc[mi][ni][1]);
            if (r1 < nloc)
                red_add_v2(out + (size_t)tk1*HID + c0, cc[mi][ni][2], cc[mi][ni][3]);
        }
    }
}

// ---------------- launch ----------------
extern "C" void kernel_launch(void* const* d_in, const int* in_sizes, int n_in,
                              void* d_out, int out_size) {
    const float* x  = (const float*)d_in[0];
    const float* rw = (const float*)d_in[1];
    const float* wg = (const float*)d_in[2];
    const float* wu = (const float*)d_in[3];
    const float* wd = (const float*)d_in[4];
    const float* sg = (const float*)d_in[5];
    const float* su = (const float*)d_in[6];
    const float* sd = (const float*)d_in[7];
    float* out = (float*)d_out;

    static bool attr_done = false;
    if (!attr_done) {
        cudaFuncSetAttribute(stage1_kernel, cudaFuncAttributeMaxDynamicSharedMemorySize, S1_SMEM);
        cudaFuncSetAttribute(stage2_kernel, cudaFuncAttributeMaxDynamicSharedMemorySize, S2_SMEM);
        attr_done = true;
    }

    zero_out_kernel<<<(T_TOK*HID/4 + 511)/512, 512>>>((float4*)out);
    router_gemm   <<<64, 256>>>(x, rw);
    zero_cnt_kernel<<<1, 64>>>();
    topk_kernel   <<<8, 256>>>();
    scan_kernel   <<<1, 64>>>();
    scatter_kernel<<<64, 256>>>();
    stage1_kernel <<<dim3(16, 66, 8),  512, S1_SMEM>>>(x, wg, wu, sg, su);
    stage2_kernel <<<dim3(16, 66, 16), 512, S2_SMEM>>>(wd, sd, out);
}